// round 6
// baseline (speedup 1.0000x reference)
#include <cuda_runtime.h>
#include <math.h>

#define NB 128
#define NC 32
#define HW 16
#define NE 4096
#define FSZ (NB*NC*HW*HW)   // 1048576

typedef unsigned long long u64;

// ---------------- scratch (device globals; no allocation) ----------------
__device__ float g_cbn[NE*NC];        // normalized codebook
__device__ int   g_hist[NE];          // last-scale histogram
__device__ float g_part[10*NB];       // per (scale, b) sum of squares

__constant__ int c_pns[10] = {1,2,3,4,5,6,8,10,13,16};

__device__ __forceinline__ u64 ffma2(u64 a, u64 b, u64 c) {
    u64 d; asm("fma.rn.f32x2 %0, %1, %2, %3;" : "=l"(d) : "l"(a), "l"(b), "l"(c));
    return d;
}
__device__ __forceinline__ u64 fadd2(u64 a, u64 b) {
    u64 d; asm("add.rn.f32x2 %0, %1, %2;" : "=l"(d) : "l"(a), "l"(b));
    return d;
}
__device__ __forceinline__ u64 pack2(float lo, float hi) {
    u64 d; asm("mov.b64 %0, {%1, %2};" : "=l"(d) : "f"(lo), "f"(hi));
    return d;
}

// ---------------- normalize codebook (+ zero histogram) ----------------
__global__ void k_cbnorm(const float* __restrict__ cb) {
    int i = blockIdx.x * 256 + threadIdx.x;
    if (i >= NE) return;
    g_hist[i] = 0;
    const float* r = cb + (size_t)i * NC;
    float s = 0.f;
#pragma unroll
    for (int c = 0; c < NC; c++) s += r[c] * r[c];
    float inv = 1.0f / fmaxf(sqrtf(s), 1e-12f);
    float* w = g_cbn + (size_t)i * NC;
#pragma unroll
    for (int c = 0; c < NC; c++) w[c] = r[c] * inv;
}

// ---------------- mega kernel: one block per image, all 10 scales ----------------
// smem layout (floats):
#define SW    0                     // 9216  : phi weights (OIHW, one k)
#define SB    9216                  // 32    : phi bias
#define SIMG  9248                  // 8192  : f_rest [c][pix]
#define SFH   17440                 // 8192  : f_hat  [c][pix]
#define SR1   25632                 // 8192  : tokens / cb tile / gathered codes
#define SHUP  33824                 // 10400 : halo'd h_up [32][325]
#define SWT   44224                 // 64    : bicubic weights
#define SJT   44288                 // 64    : bicubic indices (int)
#define SBV   44352                 // 256   : per-thread argmax value
#define SBI   44608                 // 256   : per-thread argmax index (int)
#define SIDX  44864                 // 256   : chosen code per token (int)
#define SRED  45120                 // 8     : warp loss partials
#define SM_FLOATS 45128             // 180512 bytes

__global__ __launch_bounds__(256, 1) void k_mega(
    const float* __restrict__ fin, const float* __restrict__ cb,
    const float* __restrict__ phiw, const float* __restrict__ phib,
    float* __restrict__ out, int phik_packed) {
    extern __shared__ float sm[];
    float* s_w   = sm + SW;
    float* s_bb  = sm + SB;
    float* s_img = sm + SIMG;
    float* s_fh  = sm + SFH;
    float* s_r1  = sm + SR1;
    float* s_hup = sm + SHUP;
    float* s_wt  = sm + SWT;
    int*   s_jt  = (int*)(sm + SJT);
    float* s_bv  = sm + SBV;
    int*   s_bi  = (int*)(sm + SBI);
    int*   s_idx = (int*)(sm + SIDX);
    float* s_red = sm + SRED;

    int tid = threadIdx.x, b = blockIdx.x;
    int wi = tid >> 5, lane = tid & 31;

    // load image into smem f_rest; zero f_hat
    {
        const float4* src = (const float4*)(fin + (size_t)b * 8192);
        float4* di = (float4*)s_img;
        float4* df = (float4*)s_fh;
        for (int i = tid; i < 2048; i += 256) {
            di[i] = src[i];
            df[i] = make_float4(0.f, 0.f, 0.f, 0.f);
        }
    }
    int cur_k = -1;

    for (int si = 0; si < 10; si++) {
        int pn = c_pns[si];
        int pnpn = pn * pn;
        int last = (si == 9);
        int kk_phi = (phik_packed >> (2 * si)) & 3;

        __syncthreads();   // scale boundary: prior conv/hup reads done

        // ---- phase A: weights (if changed), zero hup, tokens, bicubic tables ----
        if (kk_phi != cur_k) {
            const float4* ws = (const float4*)(phiw + (size_t)kk_phi * 9216);
            float4* wd = (float4*)s_w;
            for (int i = tid; i < 2304; i += 256) wd[i] = ws[i];
            if (tid < 32) s_bb[tid] = phib[kk_phi * 32 + tid];
            cur_k = kk_phi;
        }
        for (int i = tid; i < 10400; i += 256) s_hup[i] = 0.f;
        if (!last) {
            for (int t = tid; t < pnpn * 32; t += 256) {
                int c = t & 31, p = t >> 5;
                int py = p / pn, px = p - py * pn;
                int ys = (py * HW) / pn, ye = ((py + 1) * HW + pn - 1) / pn;
                int xs = (px * HW) / pn, xe = ((px + 1) * HW + pn - 1) / pn;
                const float* base = s_img + c * 256;
                float s = 0.f;
                for (int y = ys; y < ye; y++)
                    for (int x = xs; x < xe; x++) s += base[y * 16 + x];
                s_r1[p * 32 + c] = s / (float)((ye - ys) * (xe - xs));
            }
            if (tid < 64) {
                int i = tid >> 2, off = (tid & 3) - 1;
                double src = (i + 0.5) * (double)pn / 16.0 - 0.5;
                double i0 = floor(src);
                double f = src - i0;
                double t = fabs(f - (double)off);
                double w;
                if (t <= 1.0)      w = (1.25 * t - 2.25) * t * t + 1.0;
                else if (t < 2.0)  w = (((t - 5.0) * t + 8.0) * t - 4.0) * (-0.75);
                else               w = 0.0;
                int j = (int)i0 + off;
                j = min(max(j, 0), pn - 1);
                s_wt[tid] = (float)w;
                s_jt[tid] = j;
            }
        }
        __syncthreads();

        // ---- phase B: argmax ----
        if (pnpn == 256) {
            // one token per thread, codebook tiled through smem (broadcast reads)
            u64 tk[16];
#pragma unroll
            for (int i = 0; i < 16; i++)
                tk[i] = pack2(s_img[(2 * i) * 256 + tid], s_img[(2 * i + 1) * 256 + tid]);
            float bv = -3.4e38f; int bi = 0;
            for (int tile = 0; tile < NE; tile += 128) {
                __syncthreads();
                {
                    const float4* src = (const float4*)(g_cbn + (size_t)tile * NC);
                    float4* dst = (float4*)s_r1;
#pragma unroll
                    for (int i = 0; i < 4; i++) dst[tid + i * 256] = src[tid + i * 256];
                }
                __syncthreads();
                for (int j = 0; j < 128; j++) {
                    const ulonglong2* cr = (const ulonglong2*)(s_r1 + j * 32);
                    u64 p0 = 0ULL, p1 = 0ULL;
#pragma unroll
                    for (int i = 0; i < 8; i++) {
                        ulonglong2 v = cr[i];
                        p0 = ffma2(v.x, tk[2 * i], p0);
                        p1 = ffma2(v.y, tk[2 * i + 1], p1);
                    }
                    u64 ps = fadd2(p0, p1);
                    float2 pf = *(float2*)&ps;
                    float d = pf.x + pf.y;
                    int code = tile + j;
                    if (d > bv) { bv = d; bi = code; }
                }
            }
            s_idx[tid] = bi;
            if (last) atomicAdd(&g_hist[bi], 1);
        } else {
            // (token, code-slice) per thread; all 256 threads active
            int tok = tid % pnpn, kk = tid / pnpn;
            int nk = (255 - tok) / pnpn + 1;
            u64 tk[16];
            const ulonglong2* tp = (const ulonglong2*)(s_r1 + tok * 32);
#pragma unroll
            for (int i = 0; i < 8; i++) {
                ulonglong2 v = tp[i];
                tk[2 * i] = v.x; tk[2 * i + 1] = v.y;
            }
            int c0 = (kk * NE) / nk, c1 = ((kk + 1) * NE) / nk;
            float bv = -3.4e38f; int bi = c0;
            for (int c = c0; c < c1; c++) {
                const ulonglong2* cr = (const ulonglong2*)(g_cbn + (size_t)c * NC);
                u64 p0 = 0ULL, p1 = 0ULL;
#pragma unroll
                for (int i = 0; i < 8; i++) {
                    ulonglong2 v = cr[i];
                    p0 = ffma2(v.x, tk[2 * i], p0);
                    p1 = ffma2(v.y, tk[2 * i + 1], p1);
                }
                u64 ps = fadd2(p0, p1);
                float2 pf = *(float2*)&ps;
                float d = pf.x + pf.y;
                if (d > bv) { bv = d; bi = c; }
            }
            s_bv[tid] = bv; s_bi[tid] = bi;
            __syncthreads();
            if (tid < pnpn) {
                float v0 = s_bv[tid]; int i0 = s_bi[tid];
                for (int q = tid + pnpn; q < 256; q += pnpn) {
                    float v = s_bv[q]; int i2 = s_bi[q];
                    if (v > v0 || (v == v0 && i2 < i0)) { v0 = v; i0 = i2; }
                }
                s_idx[tid] = i0;
            }
        }
        __syncthreads();

        // ---- phase C: gather codes + (bicubic) upsample into s_hup interior ----
        if (!last) {
            for (int t = tid; t < pnpn * 32; t += 256) {
                int p = t >> 5, c = t & 31;
                s_r1[t] = cb[(size_t)s_idx[p] * NC + c];
            }
            __syncthreads();
            for (int o = tid; o < 8192; o += 256) {
                int c = o & 31, pix = o >> 5;
                int y = pix >> 4, x = pix & 15;
                float acc = 0.f;
#pragma unroll
                for (int ty = 0; ty < 4; ty++) {
                    float wy = s_wt[y * 4 + ty];
                    int jy = s_jt[y * 4 + ty];
                    const float* row = s_r1 + (jy * pn) * 32 + c;
                    float rs = 0.f;
#pragma unroll
                    for (int tx = 0; tx < 4; tx++)
                        rs = fmaf(s_wt[x * 4 + tx], row[s_jt[x * 4 + tx] * 32], rs);
                    acc = fmaf(wy, rs, acc);
                }
                s_hup[c * 325 + (y + 1) * 18 + (x + 1)] = acc;
            }
        } else {
            for (int o = tid; o < 8192; o += 256) {
                int c = o & 31, pix = o >> 5;
                int y = pix >> 4, x = pix & 15;
                s_hup[c * 325 + (y + 1) * 18 + (x + 1)] =
                    cb[(size_t)s_idx[pix] * NC + c];
            }
        }
        __syncthreads();

        // ---- phase D: 3x3 conv (f32x2 packed) + residual update + loss ----
        // warp wi owns co in [4wi,4wi+4); lane -> (y = lane>>1, xs = (lane&1)*8)
        int y = lane >> 1, xs = (lane & 1) * 8;
        u64 acc[4][4];
#pragma unroll
        for (int a = 0; a < 4; a++)
#pragma unroll
            for (int m = 0; m < 4; m++) acc[a][m] = 0ULL;

        for (int ci = 0; ci < 32; ci++) {
            const float* hp = s_hup + ci * 325 + y * 18 + xs;
            u64 pr[3][9];
#pragma unroll
            for (int r = 0; r < 3; r++) {
                float tp[10];
#pragma unroll
                for (int cc = 0; cc < 10; cc++) tp[cc] = hp[r * 18 + cc];
#pragma unroll
                for (int j = 0; j < 9; j++) pr[r][j] = pack2(tp[j], tp[j + 1]);
            }
#pragma unroll
            for (int co4 = 0; co4 < 4; co4++) {
                const float* wp = s_w + ((size_t)(wi * 4 + co4) * 32 + ci) * 9;
#pragma unroll
                for (int r = 0; r < 3; r++) {
                    u64 w0 = pack2(wp[r * 3 + 0], wp[r * 3 + 0]);
                    u64 w1 = pack2(wp[r * 3 + 1], wp[r * 3 + 1]);
                    u64 w2 = pack2(wp[r * 3 + 2], wp[r * 3 + 2]);
#pragma unroll
                    for (int m = 0; m < 4; m++) {
                        acc[co4][m] = ffma2(w0, pr[r][2 * m + 0], acc[co4][m]);
                        acc[co4][m] = ffma2(w1, pr[r][2 * m + 1], acc[co4][m]);
                        acc[co4][m] = ffma2(w2, pr[r][2 * m + 2], acc[co4][m]);
                    }
                }
            }
        }

        float sq = 0.f;
        const float* finb = fin + (size_t)b * 8192;
#pragma unroll
        for (int co4 = 0; co4 < 4; co4++) {
            int co = wi * 4 + co4;
            float bias = s_bb[co];
#pragma unroll
            for (int m = 0; m < 4; m++) {
                float2 cv = *(float2*)&acc[co4][m];
#pragma unroll
                for (int half = 0; half < 2; half++) {
                    int x = xs + 2 * m + half;
                    float conv = (half ? cv.y : cv.x) + bias;
                    float hu = s_hup[co * 325 + (y + 1) * 18 + (x + 1)];
                    float h = 0.5f * hu + 0.5f * conv;
                    int g = co * 256 + y * 16 + x;
                    float fh = s_fh[g] + h;
                    s_fh[g] = fh;
                    s_img[g] -= h;
                    float d = fh - finb[g];
                    sq = fmaf(d, d, sq);
                }
            }
        }
#pragma unroll
        for (int o = 16; o; o >>= 1) sq += __shfl_down_sync(0xffffffffu, sq, o);
        if (lane == 0) s_red[wi] = sq;
        __syncthreads();
        if (tid == 0) {
            float s = 0.f;
            for (int i = 0; i < 8; i++) s += s_red[i];
            g_part[si * NB + b] = s;
        }
    }

    // straight-through output: f_input + (f_hat - f_input)
    __syncthreads();
    {
        const float* finb = fin + (size_t)b * 8192;
        float* ob = out + (size_t)b * 8192;
        for (int i = tid; i < 8192; i += 256) {
            float fv = finb[i];
            ob[i] = fv + (s_fh[i] - fv);
        }
    }
}

// ---------------- finalize: loss + perplexity ----------------
__global__ void k_final(float* __restrict__ out, int out_size) {
    __shared__ float sr[256];
    int tid = threadIdx.x;
    float s = 0.f;
    for (int i = tid; i < 10 * NB; i += 256) s += g_part[i];
    sr[tid] = s;
    __syncthreads();
    for (int o = 128; o; o >>= 1) {
        if (tid < o) sr[tid] += sr[tid + o];
        __syncthreads();
    }
    float lossv = 0.f;
    if (tid == 0) lossv = sr[0] * (1.25f / (10.0f * (float)FSZ));
    __syncthreads();

    float e = 0.f;
    for (int i = tid; i < NE; i += 256) {
        float p = (float)g_hist[i] * (1.0f / 32768.0f);
        e += p * logf(p + 1e-10f);
    }
    sr[tid] = e;
    __syncthreads();
    for (int o = 128; o; o >>= 1) {
        if (tid < o) sr[tid] += sr[tid + o];
        __syncthreads();
    }
    if (tid == 0) {
        out[out_size - 2] = lossv;
        out[out_size - 1] = expf(-sr[0]);
    }
}

// ---------------- launcher ----------------
extern "C" void kernel_launch(void* const* d_in, const int* in_sizes, int n_in,
                              void* d_out, int out_size) {
    // Identify inputs BY SIZE (robust to metadata ordering):
    //   f_input 1048576, codebook 131072, phi_w 36864, phi_b 128
    const float* fin  = nullptr;
    const float* cb   = nullptr;
    const float* phiw = nullptr;
    const float* phib = nullptr;
    for (int i = 0; i < n_in; i++) {
        int sz = in_sizes[i];
        if      (sz == FSZ)        fin  = (const float*)d_in[i];
        else if (sz == NE * NC)    cb   = (const float*)d_in[i];
        else if (sz == 4*NC*NC*9)  phiw = (const float*)d_in[i];
        else if (sz == 4*NC)       phib = (const float*)d_in[i];
    }
    float* out = (float*)d_out;

    // PhiPartiallyShared tick schedule, replicating numpy float64 exactly.
    static const int pns[10] = {1,2,3,4,5,6,8,10,13,16};
    (void)pns;
    int phik_packed = 0;
    {
        double start = 1.0 / 12.0;
        double stop  = 1.0 - 1.0 / 12.0;
        double step  = (stop - start) / 3.0;
        double ticks[4];
        ticks[0] = start;
        ticks[1] = 1.0 * step + start;
        ticks[2] = 2.0 * step + start;
        ticks[3] = stop;
        for (int si = 0; si < 10; si++) {
            double v = (double)si / 9.0;
            int best = 0;
            double bd = fabs(ticks[0] - v);
            for (int kk = 1; kk < 4; kk++) {
                double d = fabs(ticks[kk] - v);
                if (d < bd) { bd = d; best = kk; }
            }
            phik_packed |= best << (2 * si);
        }
    }

    cudaFuncSetAttribute(k_mega, cudaFuncAttributeMaxDynamicSharedMemorySize,
                         SM_FLOATS * 4);

    k_cbnorm<<<NE / 256, 256>>>(cb);
    k_mega<<<NB, 256, SM_FLOATS * 4>>>(fin, cb, phiw, phib, out, phik_packed);
    k_final<<<1, 256>>>(out, out_size);
}

// round 7
// speedup vs baseline: 2.6591x; 2.6591x over previous
#include <cuda_runtime.h>
#include <cuda_bf16.h>
#include <math.h>

#define NB 128
#define NC 32
#define HW 16
#define NE 4096
#define FSZ (NB*NC*HW*HW)   // 1048576
#define PVCAP (256*1024)

typedef unsigned long long u64;

static const int h_PNS[10] = {1,2,3,4,5,6,8,10,13,16};

// ---------------- scratch (device globals; no allocation) ----------------
__device__ float g_cbn[NE*NC];        // normalized codebook
__device__ float g_frest[FSZ];        // residual
__device__ float g_x[FSZ];            // tokens [ntok][32]
__device__ float g_pv[PVCAP];         // partial argmax values
__device__ int   g_pi[PVCAP];         // partial argmax indices
__device__ int   g_hist[NE];          // last-scale histogram
__device__ float g_part[10*NB];       // per (scale, b) sum of squares

__device__ __forceinline__ u64 ffma2(u64 a, u64 b, u64 c) {
    u64 d; asm("fma.rn.f32x2 %0, %1, %2, %3;" : "=l"(d) : "l"(a), "l"(b), "l"(c));
    return d;
}
__device__ __forceinline__ u64 fadd2(u64 a, u64 b) {
    u64 d; asm("add.rn.f32x2 %0, %1, %2;" : "=l"(d) : "l"(a), "l"(b));
    return d;
}
__device__ __forceinline__ u64 pack2(float lo, float hi) {
    u64 d; asm("mov.b64 %0, {%1, %2};" : "=l"(d) : "f"(lo), "f"(hi));
    return d;
}

// ---------------- init: f_rest <- f_input, zero out/hist ----------------
__global__ void k_init(const float* __restrict__ fin, float* __restrict__ out,
                       int out_size) {
    int i = blockIdx.x * 256 + threadIdx.x;
    if (i < FSZ) g_frest[i] = fin[i];
    if (i < NE)  g_hist[i] = 0;
    if (i < out_size) out[i] = 0.0f;
}

// ---------------- normalize codebook ----------------
__global__ void k_cbnorm(const float* __restrict__ cb) {
    int i = blockIdx.x * 256 + threadIdx.x;
    if (i >= NE) return;
    const float* r = cb + (size_t)i * NC;
    float s = 0.f;
#pragma unroll
    for (int c = 0; c < NC; c++) s += r[c] * r[c];
    float inv = 1.0f / fmaxf(sqrtf(s), 1e-12f);
    float* w = g_cbn + (size_t)i * NC;
#pragma unroll
    for (int c = 0; c < NC; c++) w[c] = r[c] * inv;
}

// ---------------- area downsample f_rest -> tokens [ntok][C] ----------------
__global__ void k_down(int pn) {
    int t = blockIdx.x * 256 + threadIdx.x;
    int pnpn = pn * pn;
    int ntot = NB * pnpn * NC;
    if (t >= ntot) return;
    int c = t & 31, token = t >> 5;
    int b = token / pnpn, p = token - b * pnpn;
    int py = p / pn, px = p - py * pn;
    int ys = (py * HW) / pn, ye = ((py + 1) * HW + pn - 1) / pn;
    int xs = (px * HW) / pn, xe = ((px + 1) * HW + pn - 1) / pn;
    const float* base = g_frest + ((size_t)(b * NC + c)) * (HW * HW);
    float s = 0.f;
    for (int y = ys; y < ye; y++)
        for (int x = xs; x < xe; x++) s += base[y * HW + x];
    g_x[(size_t)token * NC + c] = s / (float)((ye - ys) * (xe - xs));
}

// ---------------- argmax: smem-tiled, T tokens per thread, f32x2 packed ----------
// grid = (ceil(ntok/(128*T)), CS), block = 128. cpb = 4096/CS (multiple of 128).
// pn16 != 0: read tokens transposed from g_frest (last scale, no k_down needed).
template<int T>
__global__ __launch_bounds__(128) void k_argmax_t(int ntok, int cpb, int pn16) {
    __shared__ float s_cb[128 * NC];
    int tid = threadIdx.x;
    int cbase = blockIdx.y * cpb;
    int tokbase = blockIdx.x * (128 * T) + tid;

    u64 tk[T][16];
    float bv[T]; int bi[T]; bool vld[T];
#pragma unroll
    for (int t = 0; t < T; t++) {
        int tok = tokbase + t * 128;
        vld[t] = tok < ntok;
        bv[t] = -3.4e38f; bi[t] = cbase;
#pragma unroll
        for (int i = 0; i < 16; i++) tk[t][i] = 0ULL;
        if (vld[t]) {
            if (pn16) {
                int b = tok >> 8, pix = tok & 255;
                const float* fr = g_frest + (size_t)b * 8192 + pix;
#pragma unroll
                for (int i = 0; i < 16; i++) {
                    float2 v;
                    v.x = fr[(2 * i) * 256];
                    v.y = fr[(2 * i + 1) * 256];
                    tk[t][i] = *(u64*)&v;
                }
            } else {
                const ulonglong2* p = (const ulonglong2*)(g_x + (size_t)tok * NC);
#pragma unroll
                for (int i = 0; i < 8; i++) {
                    ulonglong2 v = p[i];
                    tk[t][2 * i] = v.x; tk[t][2 * i + 1] = v.y;
                }
            }
        }
    }

    for (int tile = 0; tile < cpb; tile += 128) {
        __syncthreads();
        {
            const float4* src = (const float4*)(g_cbn + (size_t)(cbase + tile) * NC);
            float4* dst = (float4*)s_cb;
#pragma unroll
            for (int i = 0; i < 8; i++) dst[tid + i * 128] = src[tid + i * 128];
        }
        __syncthreads();
        for (int j = 0; j < 128; j++) {
            const ulonglong2* cr = (const ulonglong2*)(s_cb + j * NC);
            u64 c[16];
#pragma unroll
            for (int i = 0; i < 8; i++) {
                ulonglong2 v = cr[i];
                c[2 * i] = v.x; c[2 * i + 1] = v.y;
            }
            int code = cbase + tile + j;
#pragma unroll
            for (int t = 0; t < T; t++) {
                u64 p0 = 0ULL, p1 = 0ULL;
#pragma unroll
                for (int i = 0; i < 8; i++) {
                    p0 = ffma2(c[2 * i],     tk[t][2 * i],     p0);
                    p1 = ffma2(c[2 * i + 1], tk[t][2 * i + 1], p1);
                }
                u64 ps = fadd2(p0, p1);
                float2 pf = *(float2*)&ps;
                float d = pf.x + pf.y;
                if (d > bv[t]) { bv[t] = d; bi[t] = code; }
            }
        }
    }
    int CS = gridDim.y, cs = blockIdx.y;
#pragma unroll
    for (int t = 0; t < T; t++) {
        int tok = tokbase + t * 128;
        if (vld[t]) {
            g_pv[(size_t)tok * CS + cs] = bv[t];
            g_pi[(size_t)tok * CS + cs] = bi[t];
        }
    }
}

// -------- fused: combine partials -> gather codes -> bicubic up -> 3x3 conv -> update --
// one block per batch image b; 256 threads.
#define SW_OFF   0
#define SB_OFF   9216
#define HUP_OFF  (9216+32)
#define HS_OFF   (HUP_OFF+10400)
#define WT_OFF   (HS_OFF+8192)
#define JT_OFF   (WT_OFF+64)
#define RED_OFF  (JT_OFF+64)
#define IDX_OFF  (RED_OFF+8)
#define SMEM_FLOATS (IDX_OFF+256)

__global__ __launch_bounds__(256) void k_fused(
    const float* __restrict__ fin, float* __restrict__ fhat,
    const float* __restrict__ cb, const float* __restrict__ phiw,
    const float* __restrict__ phib, int si, int pn, int k, int last, int CS) {
    extern __shared__ float sm[];
    float* s_w   = sm + SW_OFF;
    float* s_b   = sm + SB_OFF;
    float* s_hup = sm + HUP_OFF;   // [32][325] (18x18 halo, padded stride)
    float* s_hs  = sm + HS_OFF;    // [p][c]
    float* s_wt  = sm + WT_OFF;    // bicubic weights [16][4]
    int*   s_jt  = (int*)(sm + JT_OFF);
    float* s_red = sm + RED_OFF;
    int*   s_idx = (int*)(sm + IDX_OFF);

    int tid = threadIdx.x;
    int b = blockIdx.x;
    int pnpn = pn * pn;

    // combine code-split argmax partials for this image's tokens (+ histogram)
    for (int p = tid; p < pnpn; p += 256) {
        size_t tb = (size_t)(b * pnpn + p) * CS;
        float bvv = g_pv[tb]; int bii = g_pi[tb];
        for (int cs = 1; cs < CS; cs++) {
            float v = g_pv[tb + cs]; int i2 = g_pi[tb + cs];
            if (v > bvv || (v == bvv && i2 < bii)) { bvv = v; bii = i2; }
        }
        s_idx[p] = bii;
        if (last) atomicAdd(&g_hist[bii], 1);
    }

    // load Phi weights/bias
    {
        const float4* wsrc = (const float4*)(phiw + (size_t)k * 9216);
        float4* wdst = (float4*)s_w;
        for (int i = tid; i < 2304; i += 256) wdst[i] = wsrc[i];
        if (tid < 32) s_b[tid] = phib[k * 32 + tid];
    }
    // zero halo image
    for (int i = tid; i < 10400; i += 256) s_hup[i] = 0.f;

    if (!last && tid < 64) {
        int i = tid >> 2, off = (tid & 3) - 1;
        double src = (i + 0.5) * (double)pn / 16.0 - 0.5;
        double i0 = floor(src);
        double f = src - i0;
        double t = fabs(f - (double)off);
        double w;
        if (t <= 1.0)      w = (1.25 * t - 2.25) * t * t + 1.0;
        else if (t < 2.0)  w = (((t - 5.0) * t + 8.0) * t - 4.0) * (-0.75);
        else               w = 0.0;
        int j = (int)i0 + off;
        j = min(max(j, 0), pn - 1);
        s_wt[tid] = (float)w;
        s_jt[tid] = j;
    }
    __syncthreads();

    if (!last) {
        for (int t = tid; t < pnpn * 32; t += 256) {
            int p = t >> 5, c = t & 31;
            s_hs[t] = cb[(size_t)s_idx[p] * NC + c];
        }
        __syncthreads();
    }

    // build h_up (interior of halo'd image)
    if (last) {
        for (int o = tid; o < 8192; o += 256) {
            int c = o & 31, pix = o >> 5;
            int y = pix >> 4, x = pix & 15;
            s_hup[c * 325 + (y + 1) * 18 + (x + 1)] =
                cb[(size_t)s_idx[pix] * NC + c];
        }
    } else {
        for (int o = tid; o < 8192; o += 256) {
            int c = o & 31, pix = o >> 5;
            int y = pix >> 4, x = pix & 15;
            float acc = 0.f;
#pragma unroll
            for (int ty = 0; ty < 4; ty++) {
                float wy = s_wt[y * 4 + ty];
                int jy = s_jt[y * 4 + ty];
                const float* row = s_hs + (jy * pn) * 32 + c;
                float rs = 0.f;
#pragma unroll
                for (int tx = 0; tx < 4; tx++)
                    rs = fmaf(s_wt[x * 4 + tx], row[s_jt[x * 4 + tx] * 32], rs);
                acc = fmaf(wy, rs, acc);
            }
            s_hup[c * 325 + (y + 1) * 18 + (x + 1)] = acc;
        }
    }
    __syncthreads();

    // 3x3 conv (f32x2 packed): warp wi owns co in [4wi,4wi+4);
    // lane -> (y = lane>>1, xs = (lane&1)*8); 4 f32x2 pairs per (co, lane)
    int wi = tid >> 5, lane = tid & 31;
    int y = lane >> 1, xs = (lane & 1) * 8;
    u64 acc[4][4];
#pragma unroll
    for (int a = 0; a < 4; a++)
#pragma unroll
        for (int m = 0; m < 4; m++) acc[a][m] = 0ULL;

    for (int ci = 0; ci < 32; ci++) {
        const float* hp = s_hup + ci * 325 + y * 18 + xs;
        u64 pr[3][9];
#pragma unroll
        for (int r = 0; r < 3; r++) {
            float tp[10];
#pragma unroll
            for (int cc = 0; cc < 10; cc++) tp[cc] = hp[r * 18 + cc];
#pragma unroll
            for (int j = 0; j < 9; j++) pr[r][j] = pack2(tp[j], tp[j + 1]);
        }
#pragma unroll
        for (int co4 = 0; co4 < 4; co4++) {
            const float* wp = s_w + ((size_t)(wi * 4 + co4) * 32 + ci) * 9;
#pragma unroll
            for (int r = 0; r < 3; r++) {
                u64 w0 = pack2(wp[r * 3 + 0], wp[r * 3 + 0]);
                u64 w1 = pack2(wp[r * 3 + 1], wp[r * 3 + 1]);
                u64 w2 = pack2(wp[r * 3 + 2], wp[r * 3 + 2]);
#pragma unroll
                for (int m = 0; m < 4; m++) {
                    acc[co4][m] = ffma2(w0, pr[r][2 * m + 0], acc[co4][m]);
                    acc[co4][m] = ffma2(w1, pr[r][2 * m + 1], acc[co4][m]);
                    acc[co4][m] = ffma2(w2, pr[r][2 * m + 2], acc[co4][m]);
                }
            }
        }
    }

    // h = 0.5*h_up + 0.5*(conv + bias); update f_hat, f_rest; accumulate MSE
    float sq = 0.f;
    const float* finb = fin + (size_t)b * 8192;
    float* fhb = fhat + (size_t)b * 8192;
    float* frb = g_frest + (size_t)b * 8192;
#pragma unroll
    for (int co4 = 0; co4 < 4; co4++) {
        int co = wi * 4 + co4;
        float bias = s_b[co];
#pragma unroll
        for (int m = 0; m < 4; m++) {
            float2 cv = *(float2*)&acc[co4][m];
#pragma unroll
            for (int half = 0; half < 2; half++) {
                int x = xs + 2 * m + half;
                float conv = (half ? cv.y : cv.x) + bias;
                float hu = s_hup[co * 325 + (y + 1) * 18 + (x + 1)];
                float h = 0.5f * hu + 0.5f * conv;
                int g = co * 256 + y * 16 + x;
                float fh = fhb[g] + h;
                fhb[g] = fh;
                frb[g] = frb[g] - h;
                float d = fh - finb[g];
                sq = fmaf(d, d, sq);
            }
        }
    }
#pragma unroll
    for (int o = 16; o; o >>= 1) sq += __shfl_down_sync(0xffffffffu, sq, o);
    if (lane == 0) s_red[wi] = sq;
    __syncthreads();
    if (tid == 0) {
        float s = 0.f;
        for (int i = 0; i < 8; i++) s += s_red[i];
        g_part[si * NB + b] = s;
    }
}

// ---------------- finalize: loss + perplexity ----------------
__global__ void k_final(float* __restrict__ out, int out_size) {
    __shared__ float sr[256];
    int tid = threadIdx.x;
    float s = 0.f;
    for (int i = tid; i < 10 * NB; i += 256) s += g_part[i];
    sr[tid] = s;
    __syncthreads();
    for (int o = 128; o; o >>= 1) {
        if (tid < o) sr[tid] += sr[tid + o];
        __syncthreads();
    }
    float lossv = 0.f;
    if (tid == 0) lossv = sr[0] * (1.25f / (10.0f * (float)FSZ));
    __syncthreads();

    float e = 0.f;
    for (int i = tid; i < NE; i += 256) {
        float p = (float)g_hist[i] * (1.0f / 32768.0f);
        e += p * logf(p + 1e-10f);
    }
    sr[tid] = e;
    __syncthreads();
    for (int o = 128; o; o >>= 1) {
        if (tid < o) sr[tid] += sr[tid + o];
        __syncthreads();
    }
    if (tid == 0) {
        out[out_size - 2] = lossv;
        out[out_size - 1] = expf(-sr[0]);
    }
}

// ---------------- launcher ----------------
extern "C" void kernel_launch(void* const* d_in, const int* in_sizes, int n_in,
                              void* d_out, int out_size) {
    // Identify inputs BY SIZE (robust to metadata ordering):
    //   f_input 1048576, codebook 131072, phi_w 36864, phi_b 128
    const float* fin  = nullptr;
    const float* cb   = nullptr;
    const float* phiw = nullptr;
    const float* phib = nullptr;
    for (int i = 0; i < n_in; i++) {
        int sz = in_sizes[i];
        if      (sz == FSZ)        fin  = (const float*)d_in[i];
        else if (sz == NE * NC)    cb   = (const float*)d_in[i];
        else if (sz == 4*NC*NC*9)  phiw = (const float*)d_in[i];
        else if (sz == 4*NC)       phib = (const float*)d_in[i];
    }
    float* out = (float*)d_out;

    // PhiPartiallyShared tick schedule, replicating numpy float64 exactly.
    int phik[10];
    {
        double start = 1.0 / 12.0;
        double stop  = 1.0 - 1.0 / 12.0;
        double step  = (stop - start) / 3.0;
        double ticks[4];
        ticks[0] = start;
        ticks[1] = 1.0 * step + start;
        ticks[2] = 2.0 * step + start;
        ticks[3] = stop;
        for (int si = 0; si < 10; si++) {
            double v = (double)si / 9.0;
            int best = 0;
            double bd = fabs(ticks[0] - v);
            for (int kk = 1; kk < 4; kk++) {
                double d = fabs(ticks[kk] - v);
                if (d < bd) { bd = d; best = kk; }
            }
            phik[si] = best;
        }
    }

    cudaFuncSetAttribute(k_fused, cudaFuncAttributeMaxDynamicSharedMemorySize,
                         SMEM_FLOATS * 4);

    int initN = (FSZ > out_size ? FSZ : out_size);
    k_init<<<(initN + 255) / 256, 256>>>(fin, out, out_size);
    k_cbnorm<<<(NE + 255) / 256, 256>>>(cb);

    for (int si = 0; si < 10; si++) {
        int pn = h_PNS[si];
        int ntok = NB * pn * pn;
        int last = (si == 9);

        if (!last) k_down<<<(ntok * NC + 255) / 256, 256>>>(pn);

        int CS;
        if (ntok >= 4608) {
            // T = 4 tokens/thread: 512 tokens per block
            int tb = (ntok + 511) / 512;
            CS = 1;
            while (tb * CS < 296 && CS < 32) CS <<= 1;
            dim3 g(tb, CS);
            k_argmax_t<4><<<g, 128>>>(ntok, NE / CS, last ? 1 : 0);
        } else {
            // T = 1 token/thread: 128 tokens per block
            int tb = ntok / 128;
            CS = 1;
            while (tb * CS < 296 && CS < 32) CS <<= 1;
            dim3 g(tb, CS);
            k_argmax_t<1><<<g, 128>>>(ntok, NE / CS, 0);
        }

        k_fused<<<NB, 256, SMEM_FLOATS * 4>>>(fin, out, cb, phiw, phib,
                                              si, pn, phik[si], last, CS);
    }
    k_final<<<1, 256>>>(out, out_size);
}